// round 5
// baseline (speedup 1.0000x reference)
#include <cuda_runtime.h>
#include <math.h>

#define T_STEPS 1024
#define K_FEAT  512
#define BLOCK   32
#define PF      48   // prefetch depth (register ring buffer), < ~55 HW outstanding-LDG cap

// One thread owns one (batch, feature) pair and runs the serial 2-state
// affine scan over T=1024 steps. Register ring buffer of depth PF keeps
// 48 loads in flight per thread. BLOCK=32 -> 1024 single-warp blocks:
// near-perfect wave balance across 148 SMs (7 vs 6 blocks), vs the 4-vs-3
// imbalance at BLOCK=64 that made half the SMs the tail.
// Streaming (evict-first) hints: zero-reuse data, keep L2 from thrashing.
__global__ void __launch_bounds__(BLOCK) alpha_filter_kernel(
    const float* __restrict__ in,     // [B, T, K]
    const float* __restrict__ init,   // [K]
    const float* __restrict__ tau,    // [K]
    float* __restrict__ out)          // [B, T, K]
{
    const int k = blockIdx.x * BLOCK + threadIdx.x;
    const int b = blockIdx.y;

    // Per-feature coefficients (matches reference fp32 math)
    const float tc      = fmaxf(tau[k], 1e-8f);
    const float dt_tau  = 0.001f / tc;
    const float dt_tau2 = dt_tau / tc;
    const float e       = expf(-dt_tau);

    const float a00 = e * (1.0f - dt_tau);
    const float a01 = -e * dt_tau2;
    const float a10 = e * 0.001f;
    const float a11 = e * (1.0f + dt_tau);
    const float b0  = e * dt_tau2;
    const float b1  = 1.0f - a11;

    float x0 = 0.0f;
    float x1 = init[k];

    const size_t base = (size_t)b * T_STEPS * K_FEAT + (size_t)k;
    const float* ip = in  + base;
    float*       op = out + base;

    // Prologue: fill the prefetch ring with t = 0..PF-1
    float buf[PF];
#pragma unroll
    for (int i = 0; i < PF; ++i)
        buf[i] = __ldcs(ip + (size_t)i * K_FEAT);
    ip += (size_t)PF * K_FEAT;

    // Main loop: consume step t, prefetch step t+PF.
    // Steps that still prefetch = T_STEPS - PF, processed in chunks of PF
    // plus one partial chunk.
#pragma unroll 1
    for (int done = 0; done + PF <= T_STEPS - PF; done += PF) {
#pragma unroll
        for (int i = 0; i < PF; ++i) {
            const float u = buf[i];
            buf[i] = __ldcs(ip + (size_t)i * K_FEAT);   // prefetch t + PF
            const float nx0 = fmaf(a00, x0, fmaf(a01, x1, b0 * u));
            const float nx1 = fmaf(a10, x0, fmaf(a11, x1, b1 * u));
            x0 = nx0;
            x1 = nx1;
            __stcs(op + (size_t)i * K_FEAT, nx1);
        }
        ip += (size_t)PF * K_FEAT;
        op += (size_t)PF * K_FEAT;
    }

    // Partial chunk: remaining steps that still prefetch.
    // (T_STEPS - PF) % PF = 976 % 48 = 16 steps.
#define REM ((T_STEPS - PF) % PF)
#if REM
#pragma unroll
    for (int i = 0; i < REM; ++i) {
        const float u = buf[i];
        buf[i] = __ldcs(ip + (size_t)i * K_FEAT);
        const float nx0 = fmaf(a00, x0, fmaf(a01, x1, b0 * u));
        const float nx1 = fmaf(a10, x0, fmaf(a11, x1, b1 * u));
        x0 = nx0;
        x1 = nx1;
        __stcs(op + (size_t)i * K_FEAT, nx1);
    }
    ip += (size_t)REM * K_FEAT;
    op += (size_t)REM * K_FEAT;
#endif

    // Epilogue: drain the last PF buffered inputs (no further prefetch).
    // Ring read order continues from index REM (mod PF).
#pragma unroll
    for (int i = 0; i < PF; ++i) {
        const int idx = (REM + i) % PF;
        const float u = buf[idx];
        const float nx0 = fmaf(a00, x0, fmaf(a01, x1, b0 * u));
        const float nx1 = fmaf(a10, x0, fmaf(a11, x1, b1 * u));
        x0 = nx0;
        x1 = nx1;
        __stcs(op + (size_t)i * K_FEAT, nx1);
    }
}

extern "C" void kernel_launch(void* const* d_in, const int* in_sizes, int n_in,
                              void* d_out, int out_size) {
    const float* inputs = (const float*)d_in[0];   // [B, T, K]
    const float* init   = (const float*)d_in[1];   // [K]
    const float* tau    = (const float*)d_in[2];   // [K]
    float*       out    = (float*)d_out;

    const int batch = in_sizes[0] / (T_STEPS * K_FEAT);   // 64
    dim3 grid(K_FEAT / BLOCK, batch);
    alpha_filter_kernel<<<grid, BLOCK>>>(inputs, init, tau, out);
}

// round 6
// speedup vs baseline: 1.0471x; 1.0471x over previous
#include <cuda_runtime.h>
#include <math.h>

#define T_STEPS 1024
#define K_FEAT  512
#define BLOCK   64
#define PF      52   // prefetch depth, just under ~55 outstanding-LDG/warp HW cap

// One thread owns one (batch, feature) pair; serial 2-state affine scan over
// T=1024. Register ring buffer of depth PF keeps 52 loads in flight/thread.
// BLOCK=64 (R3 config — fastest measured); stores use evict-first streaming
// hint (zero reuse), loads stay default-cached.
__global__ void __launch_bounds__(BLOCK) alpha_filter_kernel(
    const float* __restrict__ in,     // [B, T, K]
    const float* __restrict__ init,   // [K]
    const float* __restrict__ tau,    // [K]
    float* __restrict__ out)          // [B, T, K]
{
    const int k = blockIdx.x * BLOCK + threadIdx.x;
    const int b = blockIdx.y;

    // Per-feature coefficients (matches reference fp32 math)
    const float tc      = fmaxf(tau[k], 1e-8f);
    const float dt_tau  = 0.001f / tc;
    const float dt_tau2 = dt_tau / tc;
    const float e       = expf(-dt_tau);

    const float a00 = e * (1.0f - dt_tau);
    const float a01 = -e * dt_tau2;
    const float a10 = e * 0.001f;
    const float a11 = e * (1.0f + dt_tau);
    const float b0  = e * dt_tau2;
    const float b1  = 1.0f - a11;

    float x0 = 0.0f;
    float x1 = init[k];

    const size_t base = (size_t)b * T_STEPS * K_FEAT + (size_t)k;
    const float* ip = in  + base;
    float*       op = out + base;

    // Prologue: fill the prefetch ring with t = 0..PF-1
    float buf[PF];
#pragma unroll
    for (int i = 0; i < PF; ++i)
        buf[i] = ip[(size_t)i * K_FEAT];
    ip += (size_t)PF * K_FEAT;

    // Main loop: consume step t, prefetch step t+PF.
    // Steps that still prefetch = T_STEPS - PF = 972: 18 full chunks of 52
    // plus a partial chunk of 36.
#pragma unroll 1
    for (int done = 0; done + PF <= T_STEPS - PF; done += PF) {
#pragma unroll
        for (int i = 0; i < PF; ++i) {
            const float u = buf[i];
            buf[i] = ip[(size_t)i * K_FEAT];   // prefetch t + PF
            const float nx0 = fmaf(a00, x0, fmaf(a01, x1, b0 * u));
            const float nx1 = fmaf(a10, x0, fmaf(a11, x1, b1 * u));
            x0 = nx0;
            x1 = nx1;
            __stcs(op + (size_t)i * K_FEAT, nx1);
        }
        ip += (size_t)PF * K_FEAT;
        op += (size_t)PF * K_FEAT;
    }

    // Partial chunk: remaining steps that still prefetch.
#define REM ((T_STEPS - PF) % PF)
#if REM
#pragma unroll
    for (int i = 0; i < REM; ++i) {
        const float u = buf[i];
        buf[i] = ip[(size_t)i * K_FEAT];
        const float nx0 = fmaf(a00, x0, fmaf(a01, x1, b0 * u));
        const float nx1 = fmaf(a10, x0, fmaf(a11, x1, b1 * u));
        x0 = nx0;
        x1 = nx1;
        __stcs(op + (size_t)i * K_FEAT, nx1);
    }
    ip += (size_t)REM * K_FEAT;
    op += (size_t)REM * K_FEAT;
#endif

    // Epilogue: drain the last PF buffered inputs (no further prefetch).
    // Ring read order continues from index REM (mod PF).
#pragma unroll
    for (int i = 0; i < PF; ++i) {
        const int idx = (REM + i) % PF;
        const float u = buf[idx];
        const float nx0 = fmaf(a00, x0, fmaf(a01, x1, b0 * u));
        const float nx1 = fmaf(a10, x0, fmaf(a11, x1, b1 * u));
        x0 = nx0;
        x1 = nx1;
        __stcs(op + (size_t)i * K_FEAT, nx1);
    }
}

extern "C" void kernel_launch(void* const* d_in, const int* in_sizes, int n_in,
                              void* d_out, int out_size) {
    const float* inputs = (const float*)d_in[0];   // [B, T, K]
    const float* init   = (const float*)d_in[1];   // [K]
    const float* tau    = (const float*)d_in[2];   // [K]
    float*       out    = (float*)d_out;

    const int batch = in_sizes[0] / (T_STEPS * K_FEAT);   // 64
    dim3 grid(K_FEAT / BLOCK, batch);
    alpha_filter_kernel<<<grid, BLOCK>>>(inputs, init, tau, out);
}